// round 17
// baseline (speedup 1.0000x reference)
#include <cuda_runtime.h>
#include <cstdint>

// IF spiking neuron forward (R17 — probe: Blackwell 256-bit ld/st.global.v8):
//   x: [T=8, N=4194304] fp32, thresh: [1] fp32
//   mem = 0.5*thr; per t: m = mem + x[t]; s = (m>=thr); out[t] = s*thr; mem = m - s*thr
//
// Last untested lever: sm_100+ 256-bit global memops (PTX ld/st.global.v8.b32).
// Each thread owns 8 consecutive floats (32B); front-batches 8 timestep
// LDG.256 (.cg: L2-only) = 256B in flight/thread, half the memop count of the
// float4 version. Regs ~80 -> occ ~37%: R3 showed 256B/thread at low occ was
// 70.6% DRAM, but confounded by .cs hints + dual LDG.128; the wide-op issue
// reduction is the new variable.
// Decision rule: regression -> revert to R15 (.cg float4, TPB64, 35.4us best,
// 76.0% DRAM) as FINAL. Laws so far: never cap regs; .cg > default > .cs;
// fine CTAs; multi-wave > persistent.

#define T_STEPS 8
#define N_NEURONS (256 / T_STEPS * 512 * 16 * 16)   // 4,194,304 floats per timestep
#define N8 (N_NEURONS / 8)                           // 524,288 v8-chunks per timestep
#define TPB 64

__global__ __launch_bounds__(TPB) void if_forward_kernel(
    const float* __restrict__ x,
    const float* __restrict__ thresh,
    float* __restrict__ out)
{
    const int i = blockIdx.x * TPB + threadIdx.x;  // grid exactly covers N8
    const float thr = __ldg(thresh);

    const float* xp = x + (size_t)i * 8;

    // Front-batch 8 timestep LDG.256 loads (.cg = L2-only).
    uint32_t v[T_STEPS][8];
#pragma unroll
    for (int t = 0; t < T_STEPS; t++) {
        const float* p = xp + (size_t)t * N_NEURONS;
        asm volatile(
            "ld.global.cg.v8.b32 {%0,%1,%2,%3,%4,%5,%6,%7}, [%8];"
            : "=r"(v[t][0]), "=r"(v[t][1]), "=r"(v[t][2]), "=r"(v[t][3]),
              "=r"(v[t][4]), "=r"(v[t][5]), "=r"(v[t][6]), "=r"(v[t][7])
            : "l"(p));
    }

    float m[8];
#pragma unroll
    for (int j = 0; j < 8; j++) m[j] = 0.5f * thr;

    float* op = out + (size_t)i * 8;

#pragma unroll
    for (int t = 0; t < T_STEPS; t++) {
        uint32_t s[8];
#pragma unroll
        for (int j = 0; j < 8; j++) {
            m[j] += __uint_as_float(v[t][j]);
            float sp = (m[j] >= thr) ? thr : 0.0f;
            m[j] -= sp;
            s[j] = __float_as_uint(sp);
        }
        float* p = op + (size_t)t * N_NEURONS;
        asm volatile(
            "st.global.v8.b32 [%0], {%1,%2,%3,%4,%5,%6,%7,%8};"
            :: "l"(p),
               "r"(s[0]), "r"(s[1]), "r"(s[2]), "r"(s[3]),
               "r"(s[4]), "r"(s[5]), "r"(s[6]), "r"(s[7])
            : "memory");
    }
}

extern "C" void kernel_launch(void* const* d_in, const int* in_sizes, int n_in,
                              void* d_out, int out_size) {
    const float* x = (const float*)d_in[0];
    const float* thresh = (const float*)d_in[1];
    float* out = (float*)d_out;

    const int blocks = N8 / TPB;  // 8192, exact
    if_forward_kernel<<<blocks, TPB>>>(x, thresh, out);
}